// round 4
// baseline (speedup 1.0000x reference)
#include <cuda_runtime.h>

#define NN 50000
#define EE 1600000
#define DD 128
#define GEMM_BLKS 391           // ceil(50000/128)
#define SPMM_BLKS 6250          // ceil(50000/8)
#define SCAN_BLKS 196           // ceil(50000/256)

// ---------------- scratch (static device memory, allocation-free) ------------
__device__ __align__(16) int    g_degi[NN];
__device__ __align__(16) int    g_fill[NN];
__device__ __align__(16) int    g_rowptr[NN + 1];
__device__ __align__(16) float  g_dinv[NN];
__device__ __align__(16) int    g_part[256];
__device__ __align__(16) float2 g_csr[EE];          // .x = src (bits), .y = weight
__device__ __align__(16) float  g_p1[(long)NN * DD];
__device__ __align__(16) float  g_p2[(long)NN * DD];
__device__ __align__(16) float  g_p3[(long)NN * DD];
__device__ __align__(16) float  g_acc[(long)NN * DD];
__device__ __align__(16) float  g_h[(long)NN * DD];

// ---------------- degree + decoupled scan + CSR build ------------------------
__global__ void k_zero_i(int* __restrict__ p, int n) {
    int i = blockIdx.x * blockDim.x + threadIdx.x;
    if (i < n) p[i] = 0;
}

__global__ void k_deg(const int* __restrict__ col) {
    int e = blockIdx.x * blockDim.x + threadIdx.x;
    if (e < EE) atomicAdd(&g_degi[col[e]], 1);
}

// block sums of degree (196 blocks x 256)
__global__ void k_blocksum() {
    __shared__ int wsum[8];
    int tid = threadIdx.x, lane = tid & 31, wid = tid >> 5;
    int idx = blockIdx.x * 256 + tid;
    int v = (idx < NN) ? g_degi[idx] : 0;
#pragma unroll
    for (int o = 16; o > 0; o >>= 1) v += __shfl_down_sync(0xffffffffu, v, o);
    if (lane == 0) wsum[wid] = v;
    __syncthreads();
    if (tid == 0) {
        int s = 0;
#pragma unroll
        for (int w = 0; w < 8; w++) s += wsum[w];
        g_part[blockIdx.x] = s;
    }
}

// exclusive scan of the 196 partials (1 block, 256 threads)
__global__ void k_scanpart() {
    __shared__ int wsum[8];
    int tid = threadIdx.x, lane = tid & 31, wid = tid >> 5;
    int v = (tid < SCAN_BLKS) ? g_part[tid] : 0;
    int incl = v;
#pragma unroll
    for (int o = 1; o < 32; o <<= 1) {
        int t = __shfl_up_sync(0xffffffffu, incl, o);
        if (lane >= o) incl += t;
    }
    if (lane == 31) wsum[wid] = incl;
    __syncthreads();
    if (wid == 0 && lane < 8) {
        int t = wsum[lane];
        int ti = t;
#pragma unroll
        for (int o = 1; o < 8; o <<= 1) {
            int u = __shfl_up_sync(0xffu, ti, o);
            if (lane >= o) ti += u;
        }
        wsum[lane] = ti - t;
    }
    __syncthreads();
    if (tid < SCAN_BLKS) g_part[tid] = wsum[wid] + incl - v;
}

// per-block rescan + rowptr + dinv
__global__ void k_scanfinal() {
    __shared__ int wsum[8];
    int tid = threadIdx.x, lane = tid & 31, wid = tid >> 5;
    int idx = blockIdx.x * 256 + tid;
    int v = (idx < NN) ? g_degi[idx] : 0;
    int incl = v;
#pragma unroll
    for (int o = 1; o < 32; o <<= 1) {
        int t = __shfl_up_sync(0xffffffffu, incl, o);
        if (lane >= o) incl += t;
    }
    if (lane == 31) wsum[wid] = incl;
    __syncthreads();
    if (wid == 0 && lane < 8) {
        int t = wsum[lane];
        int ti = t;
#pragma unroll
        for (int o = 1; o < 8; o <<= 1) {
            int u = __shfl_up_sync(0xffu, ti, o);
            if (lane >= o) ti += u;
        }
        wsum[lane] = ti - t;
    }
    __syncthreads();
    int excl = g_part[blockIdx.x] + wsum[wid] + incl - v;
    if (idx < NN) {
        g_rowptr[idx] = excl;
        g_dinv[idx] = v > 0 ? rsqrtf((float)v) : 0.f;
    }
    if (blockIdx.x == SCAN_BLKS - 1 && tid == 255) g_rowptr[NN] = excl + v;
}

__global__ void k_fill(const int* __restrict__ row, const int* __restrict__ col) {
    int e = blockIdx.x * blockDim.x + threadIdx.x;
    if (e >= EE) return;
    int s = row[e], c = col[e];
    int p = atomicAdd(&g_fill[c], 1) + g_rowptr[c];
    float2 ent;
    ent.x = __int_as_float(s);
    ent.y = g_dinv[s] * g_dinv[c];
    g_csr[p] = ent;
}

// ---------------- SpMM block body: out[i] = sum_e w_e * cur[src_e] -----------
// One warp per node; lane owns one float4 (32*4 = 128 floats).
__device__ __forceinline__ void spmm_body(const float* __restrict__ cur,
                                          float* __restrict__ outp, int blk) {
    int node = blk * 8 + (threadIdx.x >> 5);
    if (node >= NN) return;
    int lane = threadIdx.x & 31;
    int s = __ldg(&g_rowptr[node]);
    int e = __ldg(&g_rowptr[node + 1]);

    float4 acc = make_float4(0.f, 0.f, 0.f, 0.f);
    int i = s;
    for (; i + 1 < e; i += 2) {
        float2 c0 = __ldg(&g_csr[i]);
        float2 c1 = __ldg(&g_csr[i + 1]);
        int s0 = __float_as_int(c0.x);
        int s1 = __float_as_int(c1.x);
        float4 v0 = __ldg(((const float4*)(cur + (long)s0 * DD)) + lane);
        float4 v1 = __ldg(((const float4*)(cur + (long)s1 * DD)) + lane);
        acc.x += c0.y * v0.x + c1.y * v1.x;
        acc.y += c0.y * v0.y + c1.y * v1.y;
        acc.z += c0.y * v0.z + c1.y * v1.z;
        acc.w += c0.y * v0.w + c1.y * v1.w;
    }
    if (i < e) {
        float2 c0 = __ldg(&g_csr[i]);
        int s0 = __float_as_int(c0.x);
        float4 v0 = __ldg(((const float4*)(cur + (long)s0 * DD)) + lane);
        acc.x += c0.y * v0.x;
        acc.y += c0.y * v0.y;
        acc.z += c0.y * v0.z;
        acc.w += c0.y * v0.w;
    }
    ((float4*)(outp + (long)node * DD))[lane] = acc;
}

// ---------------- GEMM block body: 128x128 tile, BK=8, 256 thr, 8x8 micro ----
// MODE 0: C = A*W (overwrite)     MODE 1: C += A*W
template <int MODE>
__device__ __forceinline__ void gemm_body(const float* __restrict__ A,
                                          const float* __restrict__ W,
                                          float* __restrict__ C, int m0) {
    __shared__ __align__(16) float As[8][128];
    __shared__ __align__(16) float Bs[8][128];

    int tid = threadIdx.x;
    int tx = tid & 15;
    int ty = tid >> 4;

    float acc[8][8];
#pragma unroll
    for (int i = 0; i < 8; i++)
#pragma unroll
        for (int j = 0; j < 8; j++) acc[i][j] = 0.f;

    int a_row = tid >> 1;
    int a_col = (tid & 1) * 4;
    int b_row = tid >> 5;
    int b_col = (tid & 31) * 4;
    int gr = m0 + a_row;

    for (int k0 = 0; k0 < 128; k0 += 8) {
        float4 av = make_float4(0.f, 0.f, 0.f, 0.f);
        if (gr < NN) av = *(const float4*)(A + (long)gr * 128 + k0 + a_col);
        As[a_col + 0][a_row] = av.x;
        As[a_col + 1][a_row] = av.y;
        As[a_col + 2][a_row] = av.z;
        As[a_col + 3][a_row] = av.w;
        *(float4*)&Bs[b_row][b_col] =
            *(const float4*)(W + (long)(k0 + b_row) * 128 + b_col);
        __syncthreads();

#pragma unroll
        for (int kk = 0; kk < 8; kk++) {
            float a[8], b[8];
            *(float4*)&a[0] = *(const float4*)&As[kk][ty * 8];
            *(float4*)&a[4] = *(const float4*)&As[kk][ty * 8 + 4];
            *(float4*)&b[0] = *(const float4*)&Bs[kk][tx * 8];
            *(float4*)&b[4] = *(const float4*)&Bs[kk][tx * 8 + 4];
#pragma unroll
            for (int i = 0; i < 8; i++)
#pragma unroll
                for (int j = 0; j < 8; j++) acc[i][j] += a[i] * b[j];
        }
        __syncthreads();
    }

#pragma unroll
    for (int i = 0; i < 8; i++) {
        int r = m0 + ty * 8 + i;
        if (r >= NN) break;
        float* cp = C + (long)r * 128 + tx * 8;
#pragma unroll
        for (int j = 0; j < 8; j += 4) {
            float4 v = make_float4(acc[i][j], acc[i][j + 1], acc[i][j + 2], acc[i][j + 3]);
            if (MODE == 1) {
                float4 o = *(const float4*)(cp + j);
                v.x += o.x; v.y += o.y; v.z += o.z; v.w += o.w;
            }
            *(float4*)(cp + j) = v;
        }
    }
}

// ---------------- fused SpMM + GEMM kernel -----------------------------------
// blocks [0, GEMM_BLKS): acc (=|+=) F @ W     blocks [GEMM_BLKS, ...): P = A_norm @ F
template <bool FIRST>
__global__ void __launch_bounds__(256, 2)
k_fused(const float* __restrict__ F, float* __restrict__ P,
        const float* __restrict__ W, float* __restrict__ acc) {
    if (blockIdx.x < GEMM_BLKS) {
        gemm_body<FIRST ? 0 : 1>(F, W, acc, blockIdx.x * 128);
    } else {
        spmm_body(F, P, blockIdx.x - GEMM_BLKS);
    }
}

// ---------------- GEMM with epilogue -----------------------------------------
// dst = [relu]( [accbuf +] A @ W + bias )
template <bool USEACC, bool RELU>
__global__ void __launch_bounds__(256, 2)
k_gemm_ep(const float* __restrict__ A, const float* __restrict__ W,
          const float* __restrict__ accbuf, const float* __restrict__ bias,
          float* __restrict__ dst) {
    __shared__ __align__(16) float As[8][128];
    __shared__ __align__(16) float Bs[8][128];

    int tid = threadIdx.x;
    int m0 = blockIdx.x * 128;
    int tx = tid & 15;
    int ty = tid >> 4;

    float acc[8][8];
#pragma unroll
    for (int i = 0; i < 8; i++)
#pragma unroll
        for (int j = 0; j < 8; j++) acc[i][j] = 0.f;

    int a_row = tid >> 1;
    int a_col = (tid & 1) * 4;
    int b_row = tid >> 5;
    int b_col = (tid & 31) * 4;
    int gr = m0 + a_row;

    for (int k0 = 0; k0 < 128; k0 += 8) {
        float4 av = make_float4(0.f, 0.f, 0.f, 0.f);
        if (gr < NN) av = *(const float4*)(A + (long)gr * 128 + k0 + a_col);
        As[a_col + 0][a_row] = av.x;
        As[a_col + 1][a_row] = av.y;
        As[a_col + 2][a_row] = av.z;
        As[a_col + 3][a_row] = av.w;
        *(float4*)&Bs[b_row][b_col] =
            *(const float4*)(W + (long)(k0 + b_row) * 128 + b_col);
        __syncthreads();

#pragma unroll
        for (int kk = 0; kk < 8; kk++) {
            float a[8], b[8];
            *(float4*)&a[0] = *(const float4*)&As[kk][ty * 8];
            *(float4*)&a[4] = *(const float4*)&As[kk][ty * 8 + 4];
            *(float4*)&b[0] = *(const float4*)&Bs[kk][tx * 8];
            *(float4*)&b[4] = *(const float4*)&Bs[kk][tx * 8 + 4];
#pragma unroll
            for (int i = 0; i < 8; i++)
#pragma unroll
                for (int j = 0; j < 8; j++) acc[i][j] += a[i] * b[j];
        }
        __syncthreads();
    }

    float bb[8];
#pragma unroll
    for (int j = 0; j < 8; j++) bb[j] = __ldg(&bias[tx * 8 + j]);

#pragma unroll
    for (int i = 0; i < 8; i++) {
        int r = m0 + ty * 8 + i;
        if (r >= NN) break;
        const float* ap = accbuf + (long)r * 128 + tx * 8;
        float* dp = dst + (long)r * 128 + tx * 8;
#pragma unroll
        for (int j = 0; j < 8; j += 4) {
            float4 v = make_float4(acc[i][j] + bb[j], acc[i][j + 1] + bb[j + 1],
                                   acc[i][j + 2] + bb[j + 2], acc[i][j + 3] + bb[j + 3]);
            if (USEACC) {
                float4 o = *(const float4*)(ap + j);
                v.x += o.x; v.y += o.y; v.z += o.z; v.w += o.w;
            }
            if (RELU) {
                v.x = fmaxf(v.x, 0.f); v.y = fmaxf(v.y, 0.f);
                v.z = fmaxf(v.z, 0.f); v.w = fmaxf(v.w, 0.f);
            }
            *(float4*)(dp + j) = v;
        }
    }
}

// ---------------- host orchestration -----------------------------------------
extern "C" void kernel_launch(void* const* d_in, const int* in_sizes, int n_in,
                              void* d_out, int out_size) {
    const float* x  = (const float*)d_in[0];
    const int*   ei = (const int*)d_in[1];
    const float* W1 = (const float*)d_in[2];
    const float* b1 = (const float*)d_in[3];
    const float* W2 = (const float*)d_in[4];
    const float* b2 = (const float*)d_in[5];
    const float* W3 = (const float*)d_in[6];
    const float* b3 = (const float*)d_in[7];
    const float* Wf = (const float*)d_in[8];
    const float* bf = (const float*)d_in[9];
    float* out = (float*)d_out;

    const int* row = ei;
    const int* col = ei + EE;

    int *p_degi, *p_fill;
    float *p_p1, *p_p2, *p_p3, *p_acc, *p_h;
    cudaGetSymbolAddress((void**)&p_degi, g_degi);
    cudaGetSymbolAddress((void**)&p_fill, g_fill);
    cudaGetSymbolAddress((void**)&p_p1, g_p1);
    cudaGetSymbolAddress((void**)&p_p2, g_p2);
    cudaGetSymbolAddress((void**)&p_p3, g_p3);
    cudaGetSymbolAddress((void**)&p_acc, g_acc);
    cudaGetSymbolAddress((void**)&p_h, g_h);

    const int egrid = (EE + 255) / 256;
    const int ngrid = (NN + 255) / 256;
    const int FUSED_BLKS = GEMM_BLKS + SPMM_BLKS;

    // --- normalization + CSR build ---
    k_zero_i<<<ngrid, 256>>>(p_degi, NN);
    k_zero_i<<<ngrid, 256>>>(p_fill, NN);
    k_deg<<<egrid, 256>>>(col);
    k_blocksum<<<SCAN_BLKS, 256>>>();
    k_scanpart<<<1, 256>>>();
    k_scanfinal<<<SCAN_BLKS, 256>>>();
    k_fill<<<egrid, 256>>>(row, col);

    const float* Ws[3] = {W1, W2, W3};
    const float* bs[3] = {b1, b2, b3};

    const float* F = x;
    for (int l = 0; l < 3; l++) {
        const float* Wl = Ws[l];
        k_fused<true><<<FUSED_BLKS, 256>>>(F, p_p1, Wl, p_acc);
        k_fused<false><<<FUSED_BLKS, 256>>>(p_p1, p_p2, Wl + DD * DD, p_acc);
        k_fused<false><<<FUSED_BLKS, 256>>>(p_p2, p_p3, Wl + 2 * DD * DD, p_acc);
        k_gemm_ep<true, true><<<GEMM_BLKS, 256>>>(p_p3, Wl + 3 * DD * DD, p_acc,
                                                  bs[l], p_h);
        F = p_h;
    }
    k_gemm_ep<false, false><<<GEMM_BLKS, 256>>>(p_h, Wf, nullptr, bf, out);
}

// round 5
// speedup vs baseline: 1.3236x; 1.3236x over previous
#include <cuda_runtime.h>

#define NN 50000
#define EE 1600000
#define DD 128
#define GEMM_BLKS 391           // ceil(50000/128)
#define SPMM_BLKS 6250          // ceil(50000/8)
#define SCAN_BLKS 196           // ceil(50000/256)

// ---------------- scratch (static device memory, allocation-free) ------------
__device__ __align__(16) int    g_degi[NN];
__device__ __align__(16) int    g_fill[NN];
__device__ __align__(16) int    g_rowptr[NN + 1];
__device__ __align__(16) float  g_dinv[NN];
__device__ __align__(16) int    g_part[256];
__device__ __align__(16) float2 g_csr[EE];          // .x = src (bits), .y = weight
__device__ __align__(16) float  g_p1[(long)NN * DD];
__device__ __align__(16) float  g_p2[(long)NN * DD];
__device__ __align__(16) float  g_p3[(long)NN * DD];
__device__ __align__(16) float  g_acc[(long)NN * DD];
__device__ __align__(16) float  g_h[(long)NN * DD];

// ---------------- degree + decoupled scan + CSR build ------------------------
__global__ void k_zero_i(int* __restrict__ p, int n) {
    int i = blockIdx.x * blockDim.x + threadIdx.x;
    if (i < n) p[i] = 0;
}

__global__ void k_deg(const int* __restrict__ col) {
    int e = blockIdx.x * blockDim.x + threadIdx.x;
    if (e < EE) atomicAdd(&g_degi[col[e]], 1);
}

__global__ void k_blocksum() {
    __shared__ int wsum[8];
    int tid = threadIdx.x, lane = tid & 31, wid = tid >> 5;
    int idx = blockIdx.x * 256 + tid;
    int v = (idx < NN) ? g_degi[idx] : 0;
#pragma unroll
    for (int o = 16; o > 0; o >>= 1) v += __shfl_down_sync(0xffffffffu, v, o);
    if (lane == 0) wsum[wid] = v;
    __syncthreads();
    if (tid == 0) {
        int s = 0;
#pragma unroll
        for (int w = 0; w < 8; w++) s += wsum[w];
        g_part[blockIdx.x] = s;
    }
}

__global__ void k_scanpart() {
    __shared__ int wsum[8];
    int tid = threadIdx.x, lane = tid & 31, wid = tid >> 5;
    int v = (tid < SCAN_BLKS) ? g_part[tid] : 0;
    int incl = v;
#pragma unroll
    for (int o = 1; o < 32; o <<= 1) {
        int t = __shfl_up_sync(0xffffffffu, incl, o);
        if (lane >= o) incl += t;
    }
    if (lane == 31) wsum[wid] = incl;
    __syncthreads();
    if (wid == 0 && lane < 8) {
        int t = wsum[lane];
        int ti = t;
#pragma unroll
        for (int o = 1; o < 8; o <<= 1) {
            int u = __shfl_up_sync(0xffu, ti, o);
            if (lane >= o) ti += u;
        }
        wsum[lane] = ti - t;
    }
    __syncthreads();
    if (tid < SCAN_BLKS) g_part[tid] = wsum[wid] + incl - v;
}

__global__ void k_scanfinal() {
    __shared__ int wsum[8];
    int tid = threadIdx.x, lane = tid & 31, wid = tid >> 5;
    int idx = blockIdx.x * 256 + tid;
    int v = (idx < NN) ? g_degi[idx] : 0;
    int incl = v;
#pragma unroll
    for (int o = 1; o < 32; o <<= 1) {
        int t = __shfl_up_sync(0xffffffffu, incl, o);
        if (lane >= o) incl += t;
    }
    if (lane == 31) wsum[wid] = incl;
    __syncthreads();
    if (wid == 0 && lane < 8) {
        int t = wsum[lane];
        int ti = t;
#pragma unroll
        for (int o = 1; o < 8; o <<= 1) {
            int u = __shfl_up_sync(0xffu, ti, o);
            if (lane >= o) ti += u;
        }
        wsum[lane] = ti - t;
    }
    __syncthreads();
    int excl = g_part[blockIdx.x] + wsum[wid] + incl - v;
    if (idx < NN) {
        g_rowptr[idx] = excl;
        g_dinv[idx] = v > 0 ? rsqrtf((float)v) : 0.f;
    }
    if (blockIdx.x == SCAN_BLKS - 1 && tid == 255) g_rowptr[NN] = excl + v;
}

__global__ void k_fill(const int* __restrict__ row, const int* __restrict__ col) {
    int e = blockIdx.x * blockDim.x + threadIdx.x;
    if (e >= EE) return;
    int s = row[e], c = col[e];
    int p = atomicAdd(&g_fill[c], 1) + g_rowptr[c];
    float2 ent;
    ent.x = __int_as_float(s);
    ent.y = g_dinv[s] * g_dinv[c];
    g_csr[p] = ent;
}

// ---------------- SpMM: out[i] = sum_{e: dst=i} w_e * cur[src_e] -------------
__global__ void __launch_bounds__(256)
k_spmm(const float* __restrict__ cur, float* __restrict__ outp) {
    int node = blockIdx.x * 8 + (threadIdx.x >> 5);
    if (node >= NN) return;
    int lane = threadIdx.x & 31;
    int s = __ldg(&g_rowptr[node]);
    int e = __ldg(&g_rowptr[node + 1]);

    float4 acc = make_float4(0.f, 0.f, 0.f, 0.f);
    int i = s;
    for (; i + 1 < e; i += 2) {
        float2 c0 = __ldg(&g_csr[i]);
        float2 c1 = __ldg(&g_csr[i + 1]);
        int s0 = __float_as_int(c0.x);
        int s1 = __float_as_int(c1.x);
        float4 v0 = __ldg(((const float4*)(cur + (long)s0 * DD)) + lane);
        float4 v1 = __ldg(((const float4*)(cur + (long)s1 * DD)) + lane);
        acc.x += c0.y * v0.x + c1.y * v1.x;
        acc.y += c0.y * v0.y + c1.y * v1.y;
        acc.z += c0.y * v0.z + c1.y * v1.z;
        acc.w += c0.y * v0.w + c1.y * v1.w;
    }
    if (i < e) {
        float2 c0 = __ldg(&g_csr[i]);
        int s0 = __float_as_int(c0.x);
        float4 v0 = __ldg(((const float4*)(cur + (long)s0 * DD)) + lane);
        acc.x += c0.y * v0.x;
        acc.y += c0.y * v0.y;
        acc.z += c0.y * v0.z;
        acc.w += c0.y * v0.w;
    }
    ((float4*)(outp + (long)node * DD))[lane] = acc;
}

// ---------------- GEMM: C[M,128] (=|+=) A[M,128] @ W[128,128] ----------------
template <int MODE>  // 0: overwrite, 1: accumulate
__global__ void __launch_bounds__(256, 2)
k_gemm(const float* __restrict__ A, const float* __restrict__ W,
       float* __restrict__ C) {
    __shared__ __align__(16) float As[8][128];
    __shared__ __align__(16) float Bs[8][128];

    int tid = threadIdx.x;
    int m0 = blockIdx.x * 128;
    int tx = tid & 15;
    int ty = tid >> 4;

    float acc[8][8];
#pragma unroll
    for (int i = 0; i < 8; i++)
#pragma unroll
        for (int j = 0; j < 8; j++) acc[i][j] = 0.f;

    int a_row = tid >> 1;
    int a_col = (tid & 1) * 4;
    int b_row = tid >> 5;
    int b_col = (tid & 31) * 4;
    int gr = m0 + a_row;

    for (int k0 = 0; k0 < 128; k0 += 8) {
        float4 av = make_float4(0.f, 0.f, 0.f, 0.f);
        if (gr < NN) av = *(const float4*)(A + (long)gr * 128 + k0 + a_col);
        As[a_col + 0][a_row] = av.x;
        As[a_col + 1][a_row] = av.y;
        As[a_col + 2][a_row] = av.z;
        As[a_col + 3][a_row] = av.w;
        *(float4*)&Bs[b_row][b_col] =
            *(const float4*)(W + (long)(k0 + b_row) * 128 + b_col);
        __syncthreads();

#pragma unroll
        for (int kk = 0; kk < 8; kk++) {
            float a[8], b[8];
            *(float4*)&a[0] = *(const float4*)&As[kk][ty * 8];
            *(float4*)&a[4] = *(const float4*)&As[kk][ty * 8 + 4];
            *(float4*)&b[0] = *(const float4*)&Bs[kk][tx * 8];
            *(float4*)&b[4] = *(const float4*)&Bs[kk][tx * 8 + 4];
#pragma unroll
            for (int i = 0; i < 8; i++)
#pragma unroll
                for (int j = 0; j < 8; j++) acc[i][j] += a[i] * b[j];
        }
        __syncthreads();
    }

#pragma unroll
    for (int i = 0; i < 8; i++) {
        int r = m0 + ty * 8 + i;
        if (r >= NN) break;
        float* cp = C + (long)r * 128 + tx * 8;
#pragma unroll
        for (int j = 0; j < 8; j += 4) {
            float4 v = make_float4(acc[i][j], acc[i][j + 1], acc[i][j + 2], acc[i][j + 3]);
            if (MODE == 1) {
                float4 o = *(const float4*)(cp + j);
                v.x += o.x; v.y += o.y; v.z += o.z; v.w += o.w;
            }
            *(float4*)(cp + j) = v;
        }
    }
}

// ---------------- GEMM with epilogue: dst = [relu]([acc +] A@W + b) ----------
template <bool USEACC, bool RELU>
__global__ void __launch_bounds__(256, 2)
k_gemm_ep(const float* __restrict__ A, const float* __restrict__ W,
          const float* __restrict__ accbuf, const float* __restrict__ bias,
          float* __restrict__ dst) {
    __shared__ __align__(16) float As[8][128];
    __shared__ __align__(16) float Bs[8][128];

    int tid = threadIdx.x;
    int m0 = blockIdx.x * 128;
    int tx = tid & 15;
    int ty = tid >> 4;

    float acc[8][8];
#pragma unroll
    for (int i = 0; i < 8; i++)
#pragma unroll
        for (int j = 0; j < 8; j++) acc[i][j] = 0.f;

    int a_row = tid >> 1;
    int a_col = (tid & 1) * 4;
    int b_row = tid >> 5;
    int b_col = (tid & 31) * 4;
    int gr = m0 + a_row;

    for (int k0 = 0; k0 < 128; k0 += 8) {
        float4 av = make_float4(0.f, 0.f, 0.f, 0.f);
        if (gr < NN) av = *(const float4*)(A + (long)gr * 128 + k0 + a_col);
        As[a_col + 0][a_row] = av.x;
        As[a_col + 1][a_row] = av.y;
        As[a_col + 2][a_row] = av.z;
        As[a_col + 3][a_row] = av.w;
        *(float4*)&Bs[b_row][b_col] =
            *(const float4*)(W + (long)(k0 + b_row) * 128 + b_col);
        __syncthreads();

#pragma unroll
        for (int kk = 0; kk < 8; kk++) {
            float a[8], b[8];
            *(float4*)&a[0] = *(const float4*)&As[kk][ty * 8];
            *(float4*)&a[4] = *(const float4*)&As[kk][ty * 8 + 4];
            *(float4*)&b[0] = *(const float4*)&Bs[kk][tx * 8];
            *(float4*)&b[4] = *(const float4*)&Bs[kk][tx * 8 + 4];
#pragma unroll
            for (int i = 0; i < 8; i++)
#pragma unroll
                for (int j = 0; j < 8; j++) acc[i][j] += a[i] * b[j];
        }
        __syncthreads();
    }

    float bb[8];
#pragma unroll
    for (int j = 0; j < 8; j++) bb[j] = __ldg(&bias[tx * 8 + j]);

#pragma unroll
    for (int i = 0; i < 8; i++) {
        int r = m0 + ty * 8 + i;
        if (r >= NN) break;
        const float* ap = accbuf + (long)r * 128 + tx * 8;
        float* dp = dst + (long)r * 128 + tx * 8;
#pragma unroll
        for (int j = 0; j < 8; j += 4) {
            float4 v = make_float4(acc[i][j] + bb[j], acc[i][j + 1] + bb[j + 1],
                                   acc[i][j + 2] + bb[j + 2], acc[i][j + 3] + bb[j + 3]);
            if (USEACC) {
                float4 o = *(const float4*)(ap + j);
                v.x += o.x; v.y += o.y; v.z += o.z; v.w += o.w;
            }
            if (RELU) {
                v.x = fmaxf(v.x, 0.f); v.y = fmaxf(v.y, 0.f);
                v.z = fmaxf(v.z, 0.f); v.w = fmaxf(v.w, 0.f);
            }
            *(float4*)(dp + j) = v;
        }
    }
}

// ---------------- stream/event resources (built once, outside capture) -------
struct OverlapRes {
    cudaStream_t s1;
    cudaEvent_t ev[16];
    OverlapRes() {
        cudaStreamCreateWithFlags(&s1, cudaStreamNonBlocking);
        for (int i = 0; i < 16; i++)
            cudaEventCreateWithFlags(&ev[i], cudaEventDisableTiming);
    }
};

// ---------------- host orchestration -----------------------------------------
extern "C" void kernel_launch(void* const* d_in, const int* in_sizes, int n_in,
                              void* d_out, int out_size) {
    static OverlapRes R;  // created on first (uncaptured) correctness call

    const float* x  = (const float*)d_in[0];
    const int*   ei = (const int*)d_in[1];
    const float* W1 = (const float*)d_in[2];
    const float* b1 = (const float*)d_in[3];
    const float* W2 = (const float*)d_in[4];
    const float* b2 = (const float*)d_in[5];
    const float* W3 = (const float*)d_in[6];
    const float* b3 = (const float*)d_in[7];
    const float* Wf = (const float*)d_in[8];
    const float* bf = (const float*)d_in[9];
    float* out = (float*)d_out;

    const int* row = ei;
    const int* col = ei + EE;

    int *p_degi, *p_fill;
    float *p_p1, *p_p2, *p_p3, *p_acc, *p_h;
    cudaGetSymbolAddress((void**)&p_degi, g_degi);
    cudaGetSymbolAddress((void**)&p_fill, g_fill);
    cudaGetSymbolAddress((void**)&p_p1, g_p1);
    cudaGetSymbolAddress((void**)&p_p2, g_p2);
    cudaGetSymbolAddress((void**)&p_p3, g_p3);
    cudaGetSymbolAddress((void**)&p_acc, g_acc);
    cudaGetSymbolAddress((void**)&p_h, g_h);

    const int egrid = (EE + 255) / 256;
    const int ngrid = (NN + 255) / 256;
    cudaStream_t s1 = R.s1;
    int evi = 0;

    // Fork s1 immediately: layer-1 gemm0 (x @ W1[0]) only needs inputs.
    cudaEventRecord(R.ev[evi], 0);
    cudaStreamWaitEvent(s1, R.ev[evi], 0);
    evi++;
    k_gemm<0><<<GEMM_BLKS, 256, 0, s1>>>(x, W1, p_acc);

    // --- normalization + CSR build (s0) ---
    k_zero_i<<<ngrid, 256>>>(p_degi, NN);
    k_zero_i<<<ngrid, 256>>>(p_fill, NN);
    k_deg<<<egrid, 256>>>(col);
    k_blocksum<<<SCAN_BLKS, 256>>>();
    k_scanpart<<<1, 256>>>();
    k_scanfinal<<<SCAN_BLKS, 256>>>();
    k_fill<<<egrid, 256>>>(row, col);

    const float* Ws[3] = {W1, W2, W3};
    const float* bs[3] = {b1, b2, b3};

    const float* F = x;
    for (int l = 0; l < 3; l++) {
        const float* Wl = Ws[l];

        if (l > 0) {
            // fork: gemm0 of this layer needs F (=h of prev layer) and acc free
            cudaEventRecord(R.ev[evi], 0);
            cudaStreamWaitEvent(s1, R.ev[evi], 0);
            evi++;
            k_gemm<0><<<GEMM_BLKS, 256, 0, s1>>>(F, Wl, p_acc);
        }

        k_spmm<<<SPMM_BLKS, 256>>>(F, p_p1);
        cudaEventRecord(R.ev[evi], 0);
        cudaStreamWaitEvent(s1, R.ev[evi], 0);
        evi++;
        k_gemm<1><<<GEMM_BLKS, 256, 0, s1>>>(p_p1, Wl + DD * DD, p_acc);

        k_spmm<<<SPMM_BLKS, 256>>>(p_p1, p_p2);
        cudaEventRecord(R.ev[evi], 0);
        cudaStreamWaitEvent(s1, R.ev[evi], 0);
        k_gemm<1><<<GEMM_BLKS, 256, 0, s1>>>(p_p2, Wl + 2 * DD * DD, p_acc);
        cudaEventRecord(R.ev[evi + 1], s1);

        k_spmm<<<SPMM_BLKS, 256>>>(p_p2, p_p3);
        cudaStreamWaitEvent(0, R.ev[evi + 1], 0);
        evi += 2;
        k_gemm_ep<true, true><<<GEMM_BLKS, 256>>>(p_p3, Wl + 3 * DD * DD, p_acc,
                                                  bs[l], p_h);
        F = p_h;
    }

    k_gemm_ep<false, false><<<GEMM_BLKS, 256>>>(p_h, Wf, nullptr, bf, out);
}

// round 6
// speedup vs baseline: 1.4271x; 1.0782x over previous
#include <cuda_runtime.h>
#include <cuda_fp16.h>

#define NN 50000
#define EE 1600000
#define DD 128
#define GEMM_BLKS 391           // ceil(50000/128)
#define SPMM_BLKS 6250          // ceil(50000/8)
#define SCAN_BLKS 196           // ceil(50000/256)

// ---------------- scratch (static device memory, allocation-free) ------------
__device__ __align__(16) int    g_degi[NN];
__device__ __align__(16) int    g_fill[NN];
__device__ __align__(16) int    g_rowptr[NN + 1];
__device__ __align__(16) float  g_dinv[NN];
__device__ __align__(16) int    g_part[256];
__device__ __align__(16) float2 g_csr[EE];          // .x = src (bits), .y = weight
__device__ __align__(16) __half g_f16[(long)NN * DD];   // gather copy of F (x or h)
__device__ __align__(16) __half g_p1[(long)NN * DD];
__device__ __align__(16) __half g_p2[(long)NN * DD];
__device__ __align__(16) __half g_p3[(long)NN * DD];
__device__ __align__(16) float  g_acc[(long)NN * DD];
__device__ __align__(16) float  g_h[(long)NN * DD];

// ---------------- degree + decoupled scan + CSR build ------------------------
__global__ void k_zero_i(int* __restrict__ p, int n) {
    int i = blockIdx.x * blockDim.x + threadIdx.x;
    if (i < n) p[i] = 0;
}

__global__ void k_deg(const int* __restrict__ col) {
    int e = blockIdx.x * blockDim.x + threadIdx.x;
    if (e < EE) atomicAdd(&g_degi[col[e]], 1);
}

__global__ void k_blocksum() {
    __shared__ int wsum[8];
    int tid = threadIdx.x, lane = tid & 31, wid = tid >> 5;
    int idx = blockIdx.x * 256 + tid;
    int v = (idx < NN) ? g_degi[idx] : 0;
#pragma unroll
    for (int o = 16; o > 0; o >>= 1) v += __shfl_down_sync(0xffffffffu, v, o);
    if (lane == 0) wsum[wid] = v;
    __syncthreads();
    if (tid == 0) {
        int s = 0;
#pragma unroll
        for (int w = 0; w < 8; w++) s += wsum[w];
        g_part[blockIdx.x] = s;
    }
}

__global__ void k_scanpart() {
    __shared__ int wsum[8];
    int tid = threadIdx.x, lane = tid & 31, wid = tid >> 5;
    int v = (tid < SCAN_BLKS) ? g_part[tid] : 0;
    int incl = v;
#pragma unroll
    for (int o = 1; o < 32; o <<= 1) {
        int t = __shfl_up_sync(0xffffffffu, incl, o);
        if (lane >= o) incl += t;
    }
    if (lane == 31) wsum[wid] = incl;
    __syncthreads();
    if (wid == 0 && lane < 8) {
        int t = wsum[lane];
        int ti = t;
#pragma unroll
        for (int o = 1; o < 8; o <<= 1) {
            int u = __shfl_up_sync(0xffu, ti, o);
            if (lane >= o) ti += u;
        }
        wsum[lane] = ti - t;
    }
    __syncthreads();
    if (tid < SCAN_BLKS) g_part[tid] = wsum[wid] + incl - v;
}

__global__ void k_scanfinal() {
    __shared__ int wsum[8];
    int tid = threadIdx.x, lane = tid & 31, wid = tid >> 5;
    int idx = blockIdx.x * 256 + tid;
    int v = (idx < NN) ? g_degi[idx] : 0;
    int incl = v;
#pragma unroll
    for (int o = 1; o < 32; o <<= 1) {
        int t = __shfl_up_sync(0xffffffffu, incl, o);
        if (lane >= o) incl += t;
    }
    if (lane == 31) wsum[wid] = incl;
    __syncthreads();
    if (wid == 0 && lane < 8) {
        int t = wsum[lane];
        int ti = t;
#pragma unroll
        for (int o = 1; o < 8; o <<= 1) {
            int u = __shfl_up_sync(0xffu, ti, o);
            if (lane >= o) ti += u;
        }
        wsum[lane] = ti - t;
    }
    __syncthreads();
    int excl = g_part[blockIdx.x] + wsum[wid] + incl - v;
    if (idx < NN) {
        g_rowptr[idx] = excl;
        g_dinv[idx] = v > 0 ? rsqrtf((float)v) : 0.f;
    }
    if (blockIdx.x == SCAN_BLKS - 1 && tid == 255) g_rowptr[NN] = excl + v;
}

__global__ void k_fill(const int* __restrict__ row, const int* __restrict__ col) {
    int e = blockIdx.x * blockDim.x + threadIdx.x;
    if (e >= EE) return;
    int s = row[e], c = col[e];
    int p = atomicAdd(&g_fill[c], 1) + g_rowptr[c];
    float2 ent;
    ent.x = __int_as_float(s);
    ent.y = g_dinv[s] * g_dinv[c];
    g_csr[p] = ent;
}

// ---------------- fp32 -> fp16 conversion (x into gather plane) --------------
__global__ void k_cvt16(const float* __restrict__ src, __half* __restrict__ dst) {
    long i = (long)blockIdx.x * blockDim.x + threadIdx.x;   // in float4 units
    const long total = (long)NN * DD / 4;
    if (i >= total) return;
    float4 v = ((const float4*)src)[i];
    __half2 a = __floats2half2_rn(v.x, v.y);
    __half2 b = __floats2half2_rn(v.z, v.w);
    uint2 o;
    o.x = *(const unsigned*)&a;
    o.y = *(const unsigned*)&b;
    ((uint2*)dst)[i] = o;
}

// ---------------- SpMM fp16: out[i] = sum_{e: dst=i} w_e * cur[src_e] --------
// One warp per node; lane owns 4 features (uint2 = 4 halves).
__global__ void __launch_bounds__(256)
k_spmm16(const __half* __restrict__ cur, __half* __restrict__ outp) {
    int node = blockIdx.x * 8 + (threadIdx.x >> 5);
    if (node >= NN) return;
    int lane = threadIdx.x & 31;
    int s = __ldg(&g_rowptr[node]);
    int e = __ldg(&g_rowptr[node + 1]);

    float4 acc = make_float4(0.f, 0.f, 0.f, 0.f);
    int i = s;
    for (; i + 1 < e; i += 2) {
        float2 c0 = __ldg(&g_csr[i]);
        float2 c1 = __ldg(&g_csr[i + 1]);
        int s0 = __float_as_int(c0.x);
        int s1 = __float_as_int(c1.x);
        uint2 r0 = __ldg(((const uint2*)(cur + (long)s0 * DD)) + lane);
        uint2 r1 = __ldg(((const uint2*)(cur + (long)s1 * DD)) + lane);
        float2 a0 = __half22float2(*(const __half2*)&r0.x);
        float2 b0 = __half22float2(*(const __half2*)&r0.y);
        float2 a1 = __half22float2(*(const __half2*)&r1.x);
        float2 b1 = __half22float2(*(const __half2*)&r1.y);
        acc.x += c0.y * a0.x + c1.y * a1.x;
        acc.y += c0.y * a0.y + c1.y * a1.y;
        acc.z += c0.y * b0.x + c1.y * b1.x;
        acc.w += c0.y * b0.y + c1.y * b1.y;
    }
    if (i < e) {
        float2 c0 = __ldg(&g_csr[i]);
        int s0 = __float_as_int(c0.x);
        uint2 r0 = __ldg(((const uint2*)(cur + (long)s0 * DD)) + lane);
        float2 a0 = __half22float2(*(const __half2*)&r0.x);
        float2 b0 = __half22float2(*(const __half2*)&r0.y);
        acc.x += c0.y * a0.x;
        acc.y += c0.y * a0.y;
        acc.z += c0.y * b0.x;
        acc.w += c0.y * b0.y;
    }
    __half2 oa = __floats2half2_rn(acc.x, acc.y);
    __half2 ob = __floats2half2_rn(acc.z, acc.w);
    uint2 o;
    o.x = *(const unsigned*)&oa;
    o.y = *(const unsigned*)&ob;
    ((uint2*)(outp + (long)node * DD))[lane] = o;
}

// ---------------- GEMM fp32 A: C[M,128] = A[M,128] @ W[128,128] --------------
__global__ void __launch_bounds__(256, 2)
k_gemm0(const float* __restrict__ A, const float* __restrict__ W,
        float* __restrict__ C) {
    __shared__ __align__(16) float As[8][128];
    __shared__ __align__(16) float Bs[8][128];

    int tid = threadIdx.x;
    int m0 = blockIdx.x * 128;
    int tx = tid & 15;
    int ty = tid >> 4;

    float acc[8][8];
#pragma unroll
    for (int i = 0; i < 8; i++)
#pragma unroll
        for (int j = 0; j < 8; j++) acc[i][j] = 0.f;

    int a_row = tid >> 1;
    int a_col = (tid & 1) * 4;
    int b_row = tid >> 5;
    int b_col = (tid & 31) * 4;
    int gr = m0 + a_row;

    for (int k0 = 0; k0 < 128; k0 += 8) {
        float4 av = make_float4(0.f, 0.f, 0.f, 0.f);
        if (gr < NN) av = *(const float4*)(A + (long)gr * 128 + k0 + a_col);
        As[a_col + 0][a_row] = av.x;
        As[a_col + 1][a_row] = av.y;
        As[a_col + 2][a_row] = av.z;
        As[a_col + 3][a_row] = av.w;
        *(float4*)&Bs[b_row][b_col] =
            *(const float4*)(W + (long)(k0 + b_row) * 128 + b_col);
        __syncthreads();

#pragma unroll
        for (int kk = 0; kk < 8; kk++) {
            float a[8], b[8];
            *(float4*)&a[0] = *(const float4*)&As[kk][ty * 8];
            *(float4*)&a[4] = *(const float4*)&As[kk][ty * 8 + 4];
            *(float4*)&b[0] = *(const float4*)&Bs[kk][tx * 8];
            *(float4*)&b[4] = *(const float4*)&Bs[kk][tx * 8 + 4];
#pragma unroll
            for (int i = 0; i < 8; i++)
#pragma unroll
                for (int j = 0; j < 8; j++) acc[i][j] += a[i] * b[j];
        }
        __syncthreads();
    }

#pragma unroll
    for (int i = 0; i < 8; i++) {
        int r = m0 + ty * 8 + i;
        if (r >= NN) break;
        float* cp = C + (long)r * 128 + tx * 8;
#pragma unroll
        for (int j = 0; j < 8; j += 4) {
            float4 v = make_float4(acc[i][j], acc[i][j + 1], acc[i][j + 2], acc[i][j + 3]);
            *(float4*)(cp + j) = v;
        }
    }
}

// ---------------- GEMM fp16 A, accumulate: C += A16 @ W ----------------------
__global__ void __launch_bounds__(256, 2)
k_gemm_h(const __half* __restrict__ A, const float* __restrict__ W,
         float* __restrict__ C) {
    __shared__ __align__(16) float As[8][128];
    __shared__ __align__(16) float Bs[8][128];

    int tid = threadIdx.x;
    int m0 = blockIdx.x * 128;
    int tx = tid & 15;
    int ty = tid >> 4;

    float acc[8][8];
#pragma unroll
    for (int i = 0; i < 8; i++)
#pragma unroll
        for (int j = 0; j < 8; j++) acc[i][j] = 0.f;

    int a_row = tid >> 1;
    int a_col = (tid & 1) * 4;
    int b_row = tid >> 5;
    int b_col = (tid & 31) * 4;
    int gr = m0 + a_row;

    for (int k0 = 0; k0 < 128; k0 += 8) {
        float4 av = make_float4(0.f, 0.f, 0.f, 0.f);
        if (gr < NN) {
            uint2 raw = *(const uint2*)(A + (long)gr * 128 + k0 + a_col);
            float2 lo = __half22float2(*(const __half2*)&raw.x);
            float2 hi = __half22float2(*(const __half2*)&raw.y);
            av = make_float4(lo.x, lo.y, hi.x, hi.y);
        }
        As[a_col + 0][a_row] = av.x;
        As[a_col + 1][a_row] = av.y;
        As[a_col + 2][a_row] = av.z;
        As[a_col + 3][a_row] = av.w;
        *(float4*)&Bs[b_row][b_col] =
            *(const float4*)(W + (long)(k0 + b_row) * 128 + b_col);
        __syncthreads();

#pragma unroll
        for (int kk = 0; kk < 8; kk++) {
            float a[8], b[8];
            *(float4*)&a[0] = *(const float4*)&As[kk][ty * 8];
            *(float4*)&a[4] = *(const float4*)&As[kk][ty * 8 + 4];
            *(float4*)&b[0] = *(const float4*)&Bs[kk][tx * 8];
            *(float4*)&b[4] = *(const float4*)&Bs[kk][tx * 8 + 4];
#pragma unroll
            for (int i = 0; i < 8; i++)
#pragma unroll
                for (int j = 0; j < 8; j++) acc[i][j] += a[i] * b[j];
        }
        __syncthreads();
    }

#pragma unroll
    for (int i = 0; i < 8; i++) {
        int r = m0 + ty * 8 + i;
        if (r >= NN) break;
        float* cp = C + (long)r * 128 + tx * 8;
#pragma unroll
        for (int j = 0; j < 8; j += 4) {
            float4 o = *(const float4*)(cp + j);
            o.x += acc[i][j + 0];
            o.y += acc[i][j + 1];
            o.z += acc[i][j + 2];
            o.w += acc[i][j + 3];
            *(float4*)(cp + j) = o;
        }
    }
}

// ---------------- layer epilogue GEMM: h/h16 = relu(acc + A16@W + b) ---------
__global__ void __launch_bounds__(256, 2)
k_gemm_ep16(const __half* __restrict__ A, const float* __restrict__ W,
            const float* __restrict__ accbuf, const float* __restrict__ bias,
            float* __restrict__ dst, __half* __restrict__ dst16) {
    __shared__ __align__(16) float As[8][128];
    __shared__ __align__(16) float Bs[8][128];

    int tid = threadIdx.x;
    int m0 = blockIdx.x * 128;
    int tx = tid & 15;
    int ty = tid >> 4;

    float acc[8][8];
#pragma unroll
    for (int i = 0; i < 8; i++)
#pragma unroll
        for (int j = 0; j < 8; j++) acc[i][j] = 0.f;

    int a_row = tid >> 1;
    int a_col = (tid & 1) * 4;
    int b_row = tid >> 5;
    int b_col = (tid & 31) * 4;
    int gr = m0 + a_row;

    for (int k0 = 0; k0 < 128; k0 += 8) {
        float4 av = make_float4(0.f, 0.f, 0.f, 0.f);
        if (gr < NN) {
            uint2 raw = *(const uint2*)(A + (long)gr * 128 + k0 + a_col);
            float2 lo = __half22float2(*(const __half2*)&raw.x);
            float2 hi = __half22float2(*(const __half2*)&raw.y);
            av = make_float4(lo.x, lo.y, hi.x, hi.y);
        }
        As[a_col + 0][a_row] = av.x;
        As[a_col + 1][a_row] = av.y;
        As[a_col + 2][a_row] = av.z;
        As[a_col + 3][a_row] = av.w;
        *(float4*)&Bs[b_row][b_col] =
            *(const float4*)(W + (long)(k0 + b_row) * 128 + b_col);
        __syncthreads();

#pragma unroll
        for (int kk = 0; kk < 8; kk++) {
            float a[8], b[8];
            *(float4*)&a[0] = *(const float4*)&As[kk][ty * 8];
            *(float4*)&a[4] = *(const float4*)&As[kk][ty * 8 + 4];
            *(float4*)&b[0] = *(const float4*)&Bs[kk][tx * 8];
            *(float4*)&b[4] = *(const float4*)&Bs[kk][tx * 8 + 4];
#pragma unroll
            for (int i = 0; i < 8; i++)
#pragma unroll
                for (int j = 0; j < 8; j++) acc[i][j] += a[i] * b[j];
        }
        __syncthreads();
    }

    float bb[8];
#pragma unroll
    for (int j = 0; j < 8; j++) bb[j] = __ldg(&bias[tx * 8 + j]);

#pragma unroll
    for (int i = 0; i < 8; i++) {
        int r = m0 + ty * 8 + i;
        if (r >= NN) break;
        const float* ap = accbuf + (long)r * 128 + tx * 8;
        float* dp = dst + (long)r * 128 + tx * 8;
        __half* hp = dst16 + (long)r * 128 + tx * 8;
#pragma unroll
        for (int j = 0; j < 8; j += 4) {
            float4 o = *(const float4*)(ap + j);
            float4 v;
            v.x = fmaxf(acc[i][j + 0] + bb[j + 0] + o.x, 0.f);
            v.y = fmaxf(acc[i][j + 1] + bb[j + 1] + o.y, 0.f);
            v.z = fmaxf(acc[i][j + 2] + bb[j + 2] + o.z, 0.f);
            v.w = fmaxf(acc[i][j + 3] + bb[j + 3] + o.w, 0.f);
            *(float4*)(dp + j) = v;
            __half2 ha = __floats2half2_rn(v.x, v.y);
            __half2 hb = __floats2half2_rn(v.z, v.w);
            uint2 u;
            u.x = *(const unsigned*)&ha;
            u.y = *(const unsigned*)&hb;
            *(uint2*)(hp + j) = u;
        }
    }
}

// ---------------- final GEMM: out = h @ Wf + bf ------------------------------
__global__ void __launch_bounds__(256, 2)
k_gemm_fin(const float* __restrict__ A, const float* __restrict__ W,
           const float* __restrict__ bias, float* __restrict__ dst) {
    __shared__ __align__(16) float As[8][128];
    __shared__ __align__(16) float Bs[8][128];

    int tid = threadIdx.x;
    int m0 = blockIdx.x * 128;
    int tx = tid & 15;
    int ty = tid >> 4;

    float acc[8][8];
#pragma unroll
    for (int i = 0; i < 8; i++)
#pragma unroll
        for (int j = 0; j < 8; j++) acc[i][j] = 0.f;

    int a_row = tid >> 1;
    int a_col = (tid & 1) * 4;
    int b_row = tid >> 5;
    int b_col = (tid & 31) * 4;
    int gr = m0 + a_row;

    for (int k0 = 0; k0 < 128; k0 += 8) {
        float4 av = make_float4(0.f, 0.f, 0.f, 0.f);
        if (gr < NN) av = *(const float4*)(A + (long)gr * 128 + k0 + a_col);
        As[a_col + 0][a_row] = av.x;
        As[a_col + 1][a_row] = av.y;
        As[a_col + 2][a_row] = av.z;
        As[a_col + 3][a_row] = av.w;
        *(float4*)&Bs[b_row][b_col] =
            *(const float4*)(W + (long)(k0 + b_row) * 128 + b_col);
        __syncthreads();

#pragma unroll
        for (int kk = 0; kk < 8; kk++) {
            float a[8], b[8];
            *(float4*)&a[0] = *(const float4*)&As[kk][ty * 8];
            *(float4*)&a[4] = *(const float4*)&As[kk][ty * 8 + 4];
            *(float4*)&b[0] = *(const float4*)&Bs[kk][tx * 8];
            *(float4*)&b[4] = *(const float4*)&Bs[kk][tx * 8 + 4];
#pragma unroll
            for (int i = 0; i < 8; i++)
#pragma unroll
                for (int j = 0; j < 8; j++) acc[i][j] += a[i] * b[j];
        }
        __syncthreads();
    }

    float bb[8];
#pragma unroll
    for (int j = 0; j < 8; j++) bb[j] = __ldg(&bias[tx * 8 + j]);

#pragma unroll
    for (int i = 0; i < 8; i++) {
        int r = m0 + ty * 8 + i;
        if (r >= NN) break;
        float* dp = dst + (long)r * 128 + tx * 8;
#pragma unroll
        for (int j = 0; j < 8; j += 4) {
            float4 v = make_float4(acc[i][j] + bb[j], acc[i][j + 1] + bb[j + 1],
                                   acc[i][j + 2] + bb[j + 2], acc[i][j + 3] + bb[j + 3]);
            *(float4*)(dp + j) = v;
        }
    }
}

// ---------------- stream/event resources (built once, outside capture) -------
struct OverlapRes {
    cudaStream_t s1;
    cudaEvent_t ev[16];
    OverlapRes() {
        cudaStreamCreateWithFlags(&s1, cudaStreamNonBlocking);
        for (int i = 0; i < 16; i++)
            cudaEventCreateWithFlags(&ev[i], cudaEventDisableTiming);
    }
};

// ---------------- host orchestration -----------------------------------------
extern "C" void kernel_launch(void* const* d_in, const int* in_sizes, int n_in,
                              void* d_out, int out_size) {
    static OverlapRes R;  // created on first (uncaptured) correctness call

    const float* x  = (const float*)d_in[0];
    const int*   ei = (const int*)d_in[1];
    const float* W1 = (const float*)d_in[2];
    const float* b1 = (const float*)d_in[3];
    const float* W2 = (const float*)d_in[4];
    const float* b2 = (const float*)d_in[5];
    const float* W3 = (const float*)d_in[6];
    const float* b3 = (const float*)d_in[7];
    const float* Wf = (const float*)d_in[8];
    const float* bf = (const float*)d_in[9];
    float* out = (float*)d_out;

    const int* row = ei;
    const int* col = ei + EE;

    int *p_degi, *p_fill;
    __half *p_f16, *p_p1, *p_p2, *p_p3;
    float *p_acc, *p_h;
    cudaGetSymbolAddress((void**)&p_degi, g_degi);
    cudaGetSymbolAddress((void**)&p_fill, g_fill);
    cudaGetSymbolAddress((void**)&p_f16, g_f16);
    cudaGetSymbolAddress((void**)&p_p1, g_p1);
    cudaGetSymbolAddress((void**)&p_p2, g_p2);
    cudaGetSymbolAddress((void**)&p_p3, g_p3);
    cudaGetSymbolAddress((void**)&p_acc, g_acc);
    cudaGetSymbolAddress((void**)&p_h, g_h);

    const int egrid = (EE + 255) / 256;
    const int ngrid = (NN + 255) / 256;
    const int cgrid = (NN * DD / 4 + 255) / 256;
    cudaStream_t s1 = R.s1;
    int evi = 0;

    // Fork s1 immediately: layer-1 gemm0 (x @ W1[0]) only needs inputs.
    cudaEventRecord(R.ev[evi], 0);
    cudaStreamWaitEvent(s1, R.ev[evi], 0);
    evi++;
    k_gemm0<<<GEMM_BLKS, 256, 0, s1>>>(x, W1, p_acc);

    // --- s0: x fp16 plane + normalization + CSR build ---
    k_cvt16<<<cgrid, 256>>>(x, p_f16);
    k_zero_i<<<ngrid, 256>>>(p_degi, NN);
    k_zero_i<<<ngrid, 256>>>(p_fill, NN);
    k_deg<<<egrid, 256>>>(col);
    k_blocksum<<<SCAN_BLKS, 256>>>();
    k_scanpart<<<1, 256>>>();
    k_scanfinal<<<SCAN_BLKS, 256>>>();
    k_fill<<<egrid, 256>>>(row, col);

    const float* Ws[3] = {W1, W2, W3};
    const float* bs[3] = {b1, b2, b3};

    const float* F = x;
    for (int l = 0; l < 3; l++) {
        const float* Wl = Ws[l];

        if (l > 0) {
            // fork: gemm0 of this layer needs F (=h) and acc free (epilogue done)
            cudaEventRecord(R.ev[evi], 0);
            cudaStreamWaitEvent(s1, R.ev[evi], 0);
            evi++;
            k_gemm0<<<GEMM_BLKS, 256, 0, s1>>>(F, Wl, p_acc);
        }

        k_spmm16<<<SPMM_BLKS, 256>>>(p_f16, p_p1);
        cudaEventRecord(R.ev[evi], 0);
        cudaStreamWaitEvent(s1, R.ev[evi], 0);
        evi++;
        k_gemm_h<<<GEMM_BLKS, 256, 0, s1>>>(p_p1, Wl + DD * DD, p_acc);

        k_spmm16<<<SPMM_BLKS, 256>>>(p_p1, p_p2);
        cudaEventRecord(R.ev[evi], 0);
        cudaStreamWaitEvent(s1, R.ev[evi], 0);
        k_gemm_h<<<GEMM_BLKS, 256, 0, s1>>>(p_p2, Wl + 2 * DD * DD, p_acc);
        cudaEventRecord(R.ev[evi + 1], s1);

        k_spmm16<<<SPMM_BLKS, 256>>>(p_p2, p_p3);
        cudaStreamWaitEvent(0, R.ev[evi + 1], 0);
        evi += 2;
        k_gemm_ep16<<<GEMM_BLKS, 256>>>(p_p3, Wl + 3 * DD * DD, p_acc,
                                        bs[l], p_h, p_f16);
        F = p_h;
    }

    k_gemm_fin<<<GEMM_BLKS, 256>>>(p_h, Wf, bf, out);
}

// round 7
// speedup vs baseline: 2.6227x; 1.8378x over previous
#include <cuda_runtime.h>
#include <cuda_fp16.h>
#include <mma.h>

using namespace nvcuda;

#define NN 50000
#define EE 1600000
#define DD 128
#define GEMM_BLKS 391           // ceil(50000/128)
#define SPMM_BLKS 6250          // ceil(50000/8)
#define SCAN_BLKS 196           // ceil(50000/256)
#define SLDA 136                // smem leading dim (halves / floats)

// ---------------- scratch (static device memory, allocation-free) ------------
__device__ __align__(16) int    g_degi[NN];
__device__ __align__(16) int    g_fill[NN];
__device__ __align__(16) int    g_rowptr[NN + 1];
__device__ __align__(16) float  g_dinv[NN];
__device__ __align__(16) int    g_part[256];
__device__ __align__(16) float2 g_csr[EE];          // .x = src (bits), .y = weight
__device__ __align__(16) __half g_f16[(long)NN * DD];   // gather/GEMM copy of F
__device__ __align__(16) __half g_p1[(long)NN * DD];
__device__ __align__(16) __half g_p2[(long)NN * DD];
__device__ __align__(16) __half g_p3[(long)NN * DD];
__device__ __align__(16) float  g_acc[(long)NN * DD];
// 13 weight matrices (3 layers x 4 hops + final), hi/lo fp16 split, [K,N] layout
__device__ __align__(16) __half g_Whi[13 * DD * DD];
__device__ __align__(16) __half g_Wlo[13 * DD * DD];

// ---------------- degree + decoupled scan + CSR build ------------------------
__global__ void k_zero_i(int* __restrict__ p, int n) {
    int i = blockIdx.x * blockDim.x + threadIdx.x;
    if (i < n) p[i] = 0;
}

__global__ void k_deg(const int* __restrict__ col) {
    int e = blockIdx.x * blockDim.x + threadIdx.x;
    if (e < EE) atomicAdd(&g_degi[col[e]], 1);
}

__global__ void k_blocksum() {
    __shared__ int wsum[8];
    int tid = threadIdx.x, lane = tid & 31, wid = tid >> 5;
    int idx = blockIdx.x * 256 + tid;
    int v = (idx < NN) ? g_degi[idx] : 0;
#pragma unroll
    for (int o = 16; o > 0; o >>= 1) v += __shfl_down_sync(0xffffffffu, v, o);
    if (lane == 0) wsum[wid] = v;
    __syncthreads();
    if (tid == 0) {
        int s = 0;
#pragma unroll
        for (int w = 0; w < 8; w++) s += wsum[w];
        g_part[blockIdx.x] = s;
    }
}

__global__ void k_scanpart() {
    __shared__ int wsum[8];
    int tid = threadIdx.x, lane = tid & 31, wid = tid >> 5;
    int v = (tid < SCAN_BLKS) ? g_part[tid] : 0;
    int incl = v;
#pragma unroll
    for (int o = 1; o < 32; o <<= 1) {
        int t = __shfl_up_sync(0xffffffffu, incl, o);
        if (lane >= o) incl += t;
    }
    if (lane == 31) wsum[wid] = incl;
    __syncthreads();
    if (wid == 0 && lane < 8) {
        int t = wsum[lane];
        int ti = t;
#pragma unroll
        for (int o = 1; o < 8; o <<= 1) {
            int u = __shfl_up_sync(0xffu, ti, o);
            if (lane >= o) ti += u;
        }
        wsum[lane] = ti - t;
    }
    __syncthreads();
    if (tid < SCAN_BLKS) g_part[tid] = wsum[wid] + incl - v;
}

__global__ void k_scanfinal() {
    __shared__ int wsum[8];
    int tid = threadIdx.x, lane = tid & 31, wid = tid >> 5;
    int idx = blockIdx.x * 256 + tid;
    int v = (idx < NN) ? g_degi[idx] : 0;
    int incl = v;
#pragma unroll
    for (int o = 1; o < 32; o <<= 1) {
        int t = __shfl_up_sync(0xffffffffu, incl, o);
        if (lane >= o) incl += t;
    }
    if (lane == 31) wsum[wid] = incl;
    __syncthreads();
    if (wid == 0 && lane < 8) {
        int t = wsum[lane];
        int ti = t;
#pragma unroll
        for (int o = 1; o < 8; o <<= 1) {
            int u = __shfl_up_sync(0xffu, ti, o);
            if (lane >= o) ti += u;
        }
        wsum[lane] = ti - t;
    }
    __syncthreads();
    int excl = g_part[blockIdx.x] + wsum[wid] + incl - v;
    if (idx < NN) {
        g_rowptr[idx] = excl;
        g_dinv[idx] = v > 0 ? rsqrtf((float)v) : 0.f;
    }
    if (blockIdx.x == SCAN_BLKS - 1 && tid == 255) g_rowptr[NN] = excl + v;
}

__global__ void k_fill(const int* __restrict__ row, const int* __restrict__ col) {
    int e = blockIdx.x * blockDim.x + threadIdx.x;
    if (e >= EE) return;
    int s = row[e], c = col[e];
    int p = atomicAdd(&g_fill[c], 1) + g_rowptr[c];
    float2 ent;
    ent.x = __int_as_float(s);
    ent.y = g_dinv[s] * g_dinv[c];
    g_csr[p] = ent;
}

// ---------------- conversions -------------------------------------------------
__global__ void k_cvt16(const float* __restrict__ src, __half* __restrict__ dst) {
    long i = (long)blockIdx.x * blockDim.x + threadIdx.x;   // float4 units
    const long total = (long)NN * DD / 4;
    if (i >= total) return;
    float4 v = ((const float4*)src)[i];
    __half2 a = __floats2half2_rn(v.x, v.y);
    __half2 b = __floats2half2_rn(v.z, v.w);
    uint2 o;
    o.x = *(const unsigned*)&a;
    o.y = *(const unsigned*)&b;
    ((uint2*)dst)[i] = o;
}

// split all 13 weight matrices into hi/lo fp16
__global__ void k_wcvt(const float* __restrict__ W1, const float* __restrict__ W2,
                       const float* __restrict__ W3, const float* __restrict__ Wf) {
    int i = blockIdx.x * blockDim.x + threadIdx.x;
    if (i >= 13 * DD * DD) return;
    int m = i >> 14;            // matrix id 0..12
    int r = i & 16383;
    const float* src;
    if (m < 4)       src = W1 + m * 16384;
    else if (m < 8)  src = W2 + (m - 4) * 16384;
    else if (m < 12) src = W3 + (m - 8) * 16384;
    else             src = Wf;
    float w = src[r];
    __half h = __float2half_rn(w);
    g_Whi[i] = h;
    g_Wlo[i] = __float2half_rn(w - __half2float(h));
}

// ---------------- SpMM fp16: out[i] = sum_{e: dst=i} w_e * cur[src_e] --------
__global__ void __launch_bounds__(256)
k_spmm16(const __half* __restrict__ cur, __half* __restrict__ outp) {
    int node = blockIdx.x * 8 + (threadIdx.x >> 5);
    if (node >= NN) return;
    int lane = threadIdx.x & 31;
    int s = __ldg(&g_rowptr[node]);
    int e = __ldg(&g_rowptr[node + 1]);

    float4 acc = make_float4(0.f, 0.f, 0.f, 0.f);
    int i = s;
    for (; i + 3 < e; i += 4) {
        float2 c0 = __ldg(&g_csr[i]);
        float2 c1 = __ldg(&g_csr[i + 1]);
        float2 c2 = __ldg(&g_csr[i + 2]);
        float2 c3 = __ldg(&g_csr[i + 3]);
        uint2 r0 = __ldg(((const uint2*)(cur + (long)__float_as_int(c0.x) * DD)) + lane);
        uint2 r1 = __ldg(((const uint2*)(cur + (long)__float_as_int(c1.x) * DD)) + lane);
        uint2 r2 = __ldg(((const uint2*)(cur + (long)__float_as_int(c2.x) * DD)) + lane);
        uint2 r3 = __ldg(((const uint2*)(cur + (long)__float_as_int(c3.x) * DD)) + lane);
        float2 a0 = __half22float2(*(const __half2*)&r0.x);
        float2 b0 = __half22float2(*(const __half2*)&r0.y);
        float2 a1 = __half22float2(*(const __half2*)&r1.x);
        float2 b1 = __half22float2(*(const __half2*)&r1.y);
        float2 a2 = __half22float2(*(const __half2*)&r2.x);
        float2 b2 = __half22float2(*(const __half2*)&r2.y);
        float2 a3 = __half22float2(*(const __half2*)&r3.x);
        float2 b3 = __half22float2(*(const __half2*)&r3.y);
        acc.x += c0.y * a0.x + c1.y * a1.x + c2.y * a2.x + c3.y * a3.x;
        acc.y += c0.y * a0.y + c1.y * a1.y + c2.y * a2.y + c3.y * a3.y;
        acc.z += c0.y * b0.x + c1.y * b1.x + c2.y * b2.x + c3.y * b3.x;
        acc.w += c0.y * b0.y + c1.y * b1.y + c2.y * b2.y + c3.y * b3.y;
    }
    for (; i < e; i++) {
        float2 c0 = __ldg(&g_csr[i]);
        uint2 r0 = __ldg(((const uint2*)(cur + (long)__float_as_int(c0.x) * DD)) + lane);
        float2 a0 = __half22float2(*(const __half2*)&r0.x);
        float2 b0 = __half22float2(*(const __half2*)&r0.y);
        acc.x += c0.y * a0.x;
        acc.y += c0.y * a0.y;
        acc.z += c0.y * b0.x;
        acc.w += c0.y * b0.y;
    }
    __half2 oa = __floats2half2_rn(acc.x, acc.y);
    __half2 ob = __floats2half2_rn(acc.z, acc.w);
    uint2 o;
    o.x = *(const unsigned*)&oa;
    o.y = *(const unsigned*)&ob;
    ((uint2*)(outp + (long)node * DD))[lane] = o;
}

// ---------------- wmma GEMM: 128x128 tile, K=128, split-W hi/lo --------------
// MODE 0: C = A@W              (write fp32 g_acc)
// MODE 1: C += A@W             (accumulate into fp32 g_acc)
// MODE 2: dst16 = relu(C + A@W + bias)   (layer epilogue, fp16 out)
// MODE 3: outp = A@W + bias    (final layer, fp32 out)
template <int MODE>
__global__ void __launch_bounds__(256)
k_wgemm(const __half* __restrict__ A, const __half* __restrict__ Whi,
        const __half* __restrict__ Wlo, float* __restrict__ C,
        const float* __restrict__ bias, __half* __restrict__ dst16,
        float* __restrict__ outp) {
    extern __shared__ __align__(16) char smem_raw[];
    __half* As = (__half*)smem_raw;          // 128 x SLDA halves
    __half* Bh = As + 128 * SLDA;
    __half* Bl = Bh + 128 * SLDA;
    float*  Cs = (float*)smem_raw;           // reused: 128 x SLDA floats

    int tid = threadIdx.x;
    int wid = tid >> 5;
    int m0 = blockIdx.x * 128;

    // stage A (guarded) + Whi + Wlo
#pragma unroll
    for (int it = 0; it < 8; it++) {
        int idx = it * 256 + tid;            // 0..2047
        int row = idx >> 4;
        int c8 = (idx & 15) << 3;            // half offset
        uint4 v = make_uint4(0u, 0u, 0u, 0u);
        if (m0 + row < NN) v = *(const uint4*)(A + (long)(m0 + row) * DD + c8);
        *(uint4*)(As + row * SLDA + c8) = v;
        *(uint4*)(Bh + row * SLDA + c8) = *(const uint4*)(Whi + row * DD + c8);
        *(uint4*)(Bl + row * SLDA + c8) = *(const uint4*)(Wlo + row * DD + c8);
    }
    __syncthreads();

    int rw = (wid >> 1) * 32;                // warp tile row: 0/32/64/96
    int cw = (wid & 1) * 64;                 // warp tile col: 0/64

    wmma::fragment<wmma::accumulator, 16, 16, 16, float> acc[2][4];
#pragma unroll
    for (int i = 0; i < 2; i++)
#pragma unroll
        for (int j = 0; j < 4; j++) wmma::fill_fragment(acc[i][j], 0.f);

#pragma unroll
    for (int k = 0; k < 8; k++) {
        wmma::fragment<wmma::matrix_a, 16, 16, 16, __half, wmma::row_major> a[2];
        wmma::load_matrix_sync(a[0], As + (rw + 0) * SLDA + k * 16, SLDA);
        wmma::load_matrix_sync(a[1], As + (rw + 16) * SLDA + k * 16, SLDA);
#pragma unroll
        for (int j = 0; j < 4; j++) {
            wmma::fragment<wmma::matrix_b, 16, 16, 16, __half, wmma::row_major> bh, bl;
            wmma::load_matrix_sync(bh, Bh + (k * 16) * SLDA + cw + j * 16, SLDA);
            wmma::load_matrix_sync(bl, Bl + (k * 16) * SLDA + cw + j * 16, SLDA);
#pragma unroll
            for (int i = 0; i < 2; i++) {
                wmma::mma_sync(acc[i][j], a[i], bh, acc[i][j]);
                wmma::mma_sync(acc[i][j], a[i], bl, acc[i][j]);
            }
        }
    }
    __syncthreads();

#pragma unroll
    for (int i = 0; i < 2; i++)
#pragma unroll
        for (int j = 0; j < 4; j++)
            wmma::store_matrix_sync(Cs + (rw + i * 16) * SLDA + cw + j * 16,
                                    acc[i][j], SLDA, wmma::mem_row_major);
    __syncthreads();

    // epilogue: 128 rows x 32 float4-cols = 4096 slots
#pragma unroll
    for (int it = 0; it < 16; it++) {
        int q = it * 256 + tid;
        int row = q >> 5;
        int c4 = (q & 31) << 2;
        int r = m0 + row;
        if (r >= NN) continue;
        const float* cp = Cs + row * SLDA + c4;
        float4 v = make_float4(cp[0], cp[1], cp[2], cp[3]);
        if (MODE == 0) {
            *(float4*)(C + (long)r * DD + c4) = v;
        } else if (MODE == 1) {
            float4 o = *(const float4*)(C + (long)r * DD + c4);
            v.x += o.x; v.y += o.y; v.z += o.z; v.w += o.w;
            *(float4*)(C + (long)r * DD + c4) = v;
        } else if (MODE == 2) {
            float4 o = *(const float4*)(C + (long)r * DD + c4);
            float4 bb = *(const float4*)(bias + c4);
            v.x = fmaxf(v.x + o.x + bb.x, 0.f);
            v.y = fmaxf(v.y + o.y + bb.y, 0.f);
            v.z = fmaxf(v.z + o.z + bb.z, 0.f);
            v.w = fmaxf(v.w + o.w + bb.w, 0.f);
            __half2 ha = __floats2half2_rn(v.x, v.y);
            __half2 hb = __floats2half2_rn(v.z, v.w);
            uint2 u;
            u.x = *(const unsigned*)&ha;
            u.y = *(const unsigned*)&hb;
            *(uint2*)(dst16 + (long)r * DD + c4) = u;
        } else {
            float4 bb = *(const float4*)(bias + c4);
            v.x += bb.x; v.y += bb.y; v.z += bb.z; v.w += bb.w;
            *(float4*)(outp + (long)r * DD + c4) = v;
        }
    }
}

// ---------------- stream/event resources (built once, outside capture) -------
struct OverlapRes {
    cudaStream_t s1;
    cudaEvent_t ev[16];
    OverlapRes() {
        cudaStreamCreateWithFlags(&s1, cudaStreamNonBlocking);
        for (int i = 0; i < 16; i++)
            cudaEventCreateWithFlags(&ev[i], cudaEventDisableTiming);
    }
};

// ---------------- host orchestration -----------------------------------------
extern "C" void kernel_launch(void* const* d_in, const int* in_sizes, int n_in,
                              void* d_out, int out_size) {
    static OverlapRes R;  // created on first (uncaptured) correctness call

    const float* x  = (const float*)d_in[0];
    const int*   ei = (const int*)d_in[1];
    const float* W1 = (const float*)d_in[2];
    const float* b1 = (const float*)d_in[3];
    const float* W2 = (const float*)d_in[4];
    const float* b2 = (const float*)d_in[5];
    const float* W3 = (const float*)d_in[6];
    const float* b3 = (const float*)d_in[7];
    const float* Wf = (const float*)d_in[8];
    const float* bf = (const float*)d_in[9];
    float* out = (float*)d_out;

    const int* row = ei;
    const int* col = ei + EE;

    int *p_degi, *p_fill;
    __half *p_f16, *p_p1, *p_p2, *p_p3, *p_Whi, *p_Wlo;
    float *p_acc;
    cudaGetSymbolAddress((void**)&p_degi, g_degi);
    cudaGetSymbolAddress((void**)&p_fill, g_fill);
    cudaGetSymbolAddress((void**)&p_f16, g_f16);
    cudaGetSymbolAddress((void**)&p_p1, g_p1);
    cudaGetSymbolAddress((void**)&p_p2, g_p2);
    cudaGetSymbolAddress((void**)&p_p3, g_p3);
    cudaGetSymbolAddress((void**)&p_acc, g_acc);
    cudaGetSymbolAddress((void**)&p_Whi, g_Whi);
    cudaGetSymbolAddress((void**)&p_Wlo, g_Wlo);

    const int SMEM_W = 3 * 128 * SLDA * 2;   // 104448 B
    static bool attr_set = false;
    if (!attr_set) {
        cudaFuncSetAttribute(k_wgemm<0>, cudaFuncAttributeMaxDynamicSharedMemorySize, SMEM_W);
        cudaFuncSetAttribute(k_wgemm<1>, cudaFuncAttributeMaxDynamicSharedMemorySize, SMEM_W);
        cudaFuncSetAttribute(k_wgemm<2>, cudaFuncAttributeMaxDynamicSharedMemorySize, SMEM_W);
        cudaFuncSetAttribute(k_wgemm<3>, cudaFuncAttributeMaxDynamicSharedMemorySize, SMEM_W);
        attr_set = true;
    }

    const int egrid = (EE + 255) / 256;
    const int ngrid = (NN + 255) / 256;
    const int cgrid = (NN * DD / 4 + 255) / 256;
    const int wgrid = (13 * DD * DD + 255) / 256;
    cudaStream_t s1 = R.s1;
    int evi = 0;

    // --- s0: conversions first (gemm0 needs them) ---
    k_cvt16<<<cgrid, 256>>>(x, p_f16);
    k_wcvt<<<wgrid, 256>>>(W1, W2, W3, Wf);

    // Fork s1: layer-1 gemm0 (x16 @ W1[0]) after conversions.
    cudaEventRecord(R.ev[evi], 0);
    cudaStreamWaitEvent(s1, R.ev[evi], 0);
    evi++;
    k_wgemm<0><<<GEMM_BLKS, 256, SMEM_W, s1>>>(p_f16, p_Whi, p_Wlo, p_acc,
                                               nullptr, nullptr, nullptr);

    // --- s0: normalization + CSR build ---
    k_zero_i<<<ngrid, 256>>>(p_degi, NN);
    k_zero_i<<<ngrid, 256>>>(p_fill, NN);
    k_deg<<<egrid, 256>>>(col);
    k_blocksum<<<SCAN_BLKS, 256>>>();
    k_scanpart<<<1, 256>>>();
    k_scanfinal<<<SCAN_BLKS, 256>>>();
    k_fill<<<egrid, 256>>>(row, col);

    const float* bs[3] = {b1, b2, b3};

    for (int l = 0; l < 3; l++) {
        __half* Wl_hi = p_Whi + (long)l * 4 * DD * DD;
        __half* Wl_lo = p_Wlo + (long)l * 4 * DD * DD;

        if (l > 0) {
            cudaEventRecord(R.ev[evi], 0);
            cudaStreamWaitEvent(s1, R.ev[evi], 0);
            evi++;
            k_wgemm<0><<<GEMM_BLKS, 256, SMEM_W, s1>>>(p_f16, Wl_hi, Wl_lo, p_acc,
                                                       nullptr, nullptr, nullptr);
        }

        k_spmm16<<<SPMM_BLKS, 256>>>(p_f16, p_p1);
        cudaEventRecord(R.ev[evi], 0);
        cudaStreamWaitEvent(s1, R.ev[evi], 0);
        evi++;
        k_wgemm<1><<<GEMM_BLKS, 256, SMEM_W, s1>>>(p_p1, Wl_hi + DD * DD,
                                                   Wl_lo + DD * DD, p_acc,
                                                   nullptr, nullptr, nullptr);

        k_spmm16<<<SPMM_BLKS, 256>>>(p_p1, p_p2);
        cudaEventRecord(R.ev[evi], 0);
        cudaStreamWaitEvent(s1, R.ev[evi], 0);
        k_wgemm<1><<<GEMM_BLKS, 256, SMEM_W, s1>>>(p_p2, Wl_hi + 2 * DD * DD,
                                                   Wl_lo + 2 * DD * DD, p_acc,
                                                   nullptr, nullptr, nullptr);
        cudaEventRecord(R.ev[evi + 1], s1);

        k_spmm16<<<SPMM_BLKS, 256>>>(p_p2, p_p3);
        cudaStreamWaitEvent(0, R.ev[evi + 1], 0);
        evi += 2;
        k_wgemm<2><<<GEMM_BLKS, 256, SMEM_W>>>(p_p3, Wl_hi + 3 * DD * DD,
                                               Wl_lo + 3 * DD * DD, p_acc,
                                               bs[l], p_f16, nullptr);
    }

    __half* Wf_hi = p_Whi + 12L * DD * DD;
    __half* Wf_lo = p_Wlo + 12L * DD * DD;
    k_wgemm<3><<<GEMM_BLKS, 256, SMEM_W>>>(p_f16, Wf_hi, Wf_lo, nullptr,
                                           bf, nullptr, out);
}